// round 16
// baseline (speedup 1.0000x reference)
#include <cuda_runtime.h>
#include <cuda_bf16.h>
#include <cuda_fp16.h>
#include <cstdint>

#define NN 100000
#define NE 1600000
#define NG 50
#define FD 128

// Scratch (allocation-free rule: __device__ globals)
__device__ float g_agg_in[(size_t)NN * FD];
__device__ float g_agg_out[(size_t)NN * FD];
__device__ float g_gp[NG * FD];
__device__ __half g_Bh[FD * 3 * FD];   // fp16 weights, layout [n=128][k=384]
// CSR binning scratch
__device__ int g_cnt_in[NN],  g_cnt_out[NN];
__device__ int g_off_in[NN],  g_off_out[NN];
__device__ int g_cur_in[NN],  g_cur_out[NN];
__device__ int g_bin_in[NE],  g_bin_out[NE];

// ---------------------------------------------------------------------------
__device__ __forceinline__ uint32_t smem_u32(const void* p) {
    uint32_t a;
    asm("{ .reg .u64 t; cvta.to.shared.u64 t, %1; cvt.u32.u64 %0, t; }"
        : "=r"(a) : "l"(p));
    return a;
}
__device__ __forceinline__ uint32_t pack_f16(float x, float y) {
    __half2 t = __floats2half2_rn(x, y);   // .x = low half
    return *(uint32_t*)&t;
}

// ---------------------------------------------------------------------------
// CSR build (verbatim R14)
// ---------------------------------------------------------------------------
__global__ void init_counts_kernel() {
    int i = blockIdx.x * blockDim.x + threadIdx.x;
    if (i < NN) { g_cnt_in[i] = 0; g_cnt_out[i] = 0; }
}

__global__ void hist_kernel(const int* __restrict__ recv,
                            const int* __restrict__ send) {
    int e = blockIdx.x * blockDim.x + threadIdx.x;
    if (e < NE) {
        atomicAdd(&g_cnt_in[recv[e]], 1);
        atomicAdd(&g_cnt_out[send[e]], 1);
    }
}

#define SCAN_C 98
__global__ void scan_kernel() {
    const int* cnt = blockIdx.x ? g_cnt_out : g_cnt_in;
    int* off = blockIdx.x ? g_off_out : g_off_in;
    int* cur = blockIdx.x ? g_cur_out : g_cur_in;
    const int tid = threadIdx.x;
    const int base = tid * SCAN_C;
    int s = 0;
    for (int i = 0; i < SCAN_C; i++) {
        int idx = base + i;
        if (idx < NN) s += cnt[idx];
    }
    __shared__ int sh[1024];
    sh[tid] = s;
    __syncthreads();
    for (int o = 1; o < 1024; o <<= 1) {
        int v = (tid >= o) ? sh[tid - o] : 0;
        __syncthreads();
        sh[tid] += v;
        __syncthreads();
    }
    int run = sh[tid] - s;
    for (int i = 0; i < SCAN_C; i++) {
        int idx = base + i;
        if (idx < NN) {
            off[idx] = run;
            cur[idx] = run;
            run += cnt[idx];
        }
    }
}

__global__ void fill_kernel(const int* __restrict__ recv,
                            const int* __restrict__ send) {
    int e = blockIdx.x * blockDim.x + threadIdx.x;
    if (e < NE) {
        int p = atomicAdd(&g_cur_in[recv[e]], 1);
        g_bin_in[p] = e;
        int q = atomicAdd(&g_cur_out[send[e]], 1);
        g_bin_out[q] = e;
    }
}

// ---------------------------------------------------------------------------
// Gather: warp per node per direction; 16 edge rows in flight (MLP=16).
// Index loads are SCALAR (CSR offsets are not 16B-aligned).
// ---------------------------------------------------------------------------
__global__ void __launch_bounds__(256)
gather_kernel(const float* __restrict__ ef) {
    const int warp = threadIdx.x >> 5;
    const int lane = threadIdx.x & 31;
    const int node = blockIdx.x * 8 + warp;
    if (node >= NN) return;
    const int* off; const int* cnt; const int* bin; float* agg;
    if (blockIdx.y == 0) { off = g_off_in;  cnt = g_cnt_in;  bin = g_bin_in;  agg = g_agg_in; }
    else                 { off = g_off_out; cnt = g_cnt_out; bin = g_bin_out; agg = g_agg_out; }

    const int start = __ldg(off + node);
    const int end   = start + __ldg(cnt + node);
    const float4* ef4 = (const float4*)ef;
    float4 acc = make_float4(0.f, 0.f, 0.f, 0.f);

    int j = start;
    // 16-wide batches: preload indices (scalar), issue all 16 row loads, reduce
    for (; j + 16 <= end; j += 16) {
        int idx[16];
        #pragma unroll
        for (int q = 0; q < 16; q++)
            idx[q] = __ldg(bin + j + q);
        float4 v[16];
        #pragma unroll
        for (int q = 0; q < 16; q++)
            v[q] = __ldg(ef4 + (size_t)idx[q] * 32 + lane);
        #pragma unroll
        for (int q = 0; q < 8; q++) {
            v[q].x += v[q + 8].x; v[q].y += v[q + 8].y;
            v[q].z += v[q + 8].z; v[q].w += v[q + 8].w;
        }
        #pragma unroll
        for (int q = 0; q < 4; q++) {
            v[q].x += v[q + 4].x; v[q].y += v[q + 4].y;
            v[q].z += v[q + 4].z; v[q].w += v[q + 4].w;
        }
        float4 s0, s1;
        s0.x = v[0].x + v[1].x; s0.y = v[0].y + v[1].y;
        s0.z = v[0].z + v[1].z; s0.w = v[0].w + v[1].w;
        s1.x = v[2].x + v[3].x; s1.y = v[2].y + v[3].y;
        s1.z = v[2].z + v[3].z; s1.w = v[2].w + v[3].w;
        acc.x += s0.x + s1.x; acc.y += s0.y + s1.y;
        acc.z += s0.z + s1.z; acc.w += s0.w + s1.w;
    }
    // 4-wide tail
    for (; j + 4 <= end; j += 4) {
        int i0 = __ldg(bin + j), i1 = __ldg(bin + j + 1);
        int i2 = __ldg(bin + j + 2), i3 = __ldg(bin + j + 3);
        float4 v0 = __ldg(ef4 + (size_t)i0 * 32 + lane);
        float4 v1 = __ldg(ef4 + (size_t)i1 * 32 + lane);
        float4 v2 = __ldg(ef4 + (size_t)i2 * 32 + lane);
        float4 v3 = __ldg(ef4 + (size_t)i3 * 32 + lane);
        acc.x += (v0.x + v1.x) + (v2.x + v3.x);
        acc.y += (v0.y + v1.y) + (v2.y + v3.y);
        acc.z += (v0.z + v1.z) + (v2.z + v3.z);
        acc.w += (v0.w + v1.w) + (v2.w + v3.w);
    }
    // scalar tail
    for (; j < end; j++) {
        int i0 = __ldg(bin + j);
        float4 v = __ldg(ef4 + (size_t)i0 * 32 + lane);
        acc.x += v.x; acc.y += v.y; acc.z += v.z; acc.w += v.w;
    }
    ((float4*)(agg + (size_t)node * FD))[lane] = acc;
}

// ---------------------------------------------------------------------------
// globproj (verbatim R14)
// ---------------------------------------------------------------------------
__global__ void __launch_bounds__(256)
globproj_kernel(const float* __restrict__ gf,
                const float* __restrict__ Wg,
                const float* __restrict__ bias) {
    const int warp = threadIdx.x >> 5;
    const int lane = threadIdx.x & 31;
    const int idx = blockIdx.x * 8 + warp;
    if (idx >= NG * FD) return;
    const int g = idx >> 7, n = idx & 127;
    const float* gr = gf + (size_t)g * FD;
    const float* wr = Wg + (size_t)n * FD;
    float s = 0.f;
    #pragma unroll
    for (int q = 0; q < 4; q++)
        s += __ldg(gr + lane + q * 32) * __ldg(wr + lane + q * 32);
    #pragma unroll
    for (int o = 16; o > 0; o >>= 1) s += __shfl_xor_sync(0xFFFFFFFFu, s, o);
    if (lane == 0) g_gp[idx] = s + __ldg(bias + n);
}

// ---------------------------------------------------------------------------
// B -> fp16, layout [n][384] (verbatim R14)
// ---------------------------------------------------------------------------
__global__ void b_split_kernel(const float* __restrict__ Wn,
                               const float* __restrict__ Wi,
                               const float* __restrict__ Wo) {
    int idx = blockIdx.x * blockDim.x + threadIdx.x;
    if (idx >= FD * 3 * FD) return;
    int n = idx / (3 * FD);
    int k = idx % (3 * FD);
    int seg = k >> 7, kk = k & 127;
    const float* W = (seg == 0) ? Wn : (seg == 1) ? Wi : Wo;
    g_Bh[idx] = __float2half_rn(W[n * FD + kk]);
}

// ---------------------------------------------------------------------------
// GEMM (verbatim R14): mma.sync m16n8k16 fp16 single-term, pipelined
// ---------------------------------------------------------------------------
#define KP 40
#define TILE_BYTES (128 * KP * 2)        // 10240
#define STAGE_BYTES (2 * TILE_BYTES)     // 20480 (A + B)
#define AH_OFF(s) ((s) * STAGE_BYTES)
#define BH_OFF(s) ((s) * STAGE_BYTES + TILE_BYTES)
#define GEMM_SMEM (2 * STAGE_BYTES)      // 40960

#define MMA_F16(acc, a0, a1, a2, a3, b0, b1)                                \
    asm volatile(                                                           \
        "mma.sync.aligned.m16n8k16.row.col.f32.f16.f16.f32 "                \
        "{%0,%1,%2,%3}, {%4,%5,%6,%7}, {%8,%9}, {%0,%1,%2,%3};"             \
        : "+f"(acc[0]), "+f"(acc[1]), "+f"(acc[2]), "+f"(acc[3])            \
        : "r"(a0), "r"(a1), "r"(a2), "r"(a3), "r"(b0), "r"(b1))

__global__ void __launch_bounds__(256, 2)
gemm_mma_kernel(const float* __restrict__ node,
                const int* __restrict__ gidx,
                float* __restrict__ out) {
    extern __shared__ __align__(16) char smem[];
    const uint32_t sb = smem_u32(smem);
    __half* const smh = (__half*)smem;

    const int tid    = threadIdx.x;
    const int wid    = tid >> 5;
    const int lane   = tid & 31;
    const int gid    = lane >> 2;
    const int t2     = (lane & 3) * 2;
    const int warp_m = (wid & 3) * 32;
    const int warp_n = (wid >> 2) * 64;
    const int m0     = blockIdx.x * 128;

    const int arow  = tid >> 1;
    const int ahalf = tid & 1;
    const int gm    = m0 + arow;

    float acc[16][4];
    #pragma unroll
    for (int i = 0; i < 16; i++)
        #pragma unroll
        for (int j = 0; j < 4; j++) acc[i][j] = 0.f;

    auto load_B = [&](int kb, int st) {
        const int kglob = (kb >> 2) * FD + (kb & 3) * 32;
        #pragma unroll
        for (int i = 0; i < 2; i++) {
            int c = tid * 2 + i;
            int row = c >> 2, sub = c & 3;
            uint32_t doff = (uint32_t)(row * (KP * 2) + sub * 16);
            const __half* sh = g_Bh + (size_t)row * (3 * FD) + kglob + sub * 8;
            asm volatile("cp.async.cg.shared.global [%0], [%1], 16;"
                         :: "r"(sb + BH_OFF(st) + doff), "l"(sh) : "memory");
        }
        asm volatile("cp.async.commit_group;" ::: "memory");
    };
    auto load_A = [&](int kb, float4* v) {
        const int seg  = kb >> 2;
        const int kloc = (kb & 3) * 32;
        const float* X = (seg == 0) ? node : (seg == 1) ? g_agg_in : g_agg_out;
        #pragma unroll
        for (int j = 0; j < 4; j++) {
            if (gm < NN)
                v[j] = *(const float4*)(X + (size_t)gm * FD + kloc + ahalf * 16 + j * 4);
            else
                v[j] = make_float4(0.f, 0.f, 0.f, 0.f);
        }
    };
    auto store_A = [&](const float4* v, int st) {
        uint32_t hw[8];
        #pragma unroll
        for (int j = 0; j < 4; j++) {
            hw[j * 2 + 0] = pack_f16(v[j].x, v[j].y);
            hw[j * 2 + 1] = pack_f16(v[j].z, v[j].w);
        }
        __half* ah = smh + (AH_OFF(st) >> 1) + arow * KP + ahalf * 16;
        *(uint4*)(ah)     = make_uint4(hw[0], hw[1], hw[2], hw[3]);
        *(uint4*)(ah + 8) = make_uint4(hw[4], hw[5], hw[6], hw[7]);
    };

    {
        float4 v[4];
        load_B(0, 0);
        load_A(0, v);
        store_A(v, 0);
        asm volatile("cp.async.wait_group 0;" ::: "memory");
        __syncthreads();
    }

    #pragma unroll 1
    for (int kb = 0; kb < 12; kb++) {
        const int s = kb & 1;
        float4 v[4];
        const bool have_next = (kb < 11);
        if (have_next) {
            load_A(kb + 1, v);
            load_B(kb + 1, s ^ 1);
        }

        const __half* Ash = smh + (AH_OFF(s) >> 1);
        const __half* Bsh = smh + (BH_OFF(s) >> 1);
        #pragma unroll
        for (int ks = 0; ks < 2; ks++) {
            const int kofs = ks * 16 + t2;
            uint32_t ah[2][4];
            #pragma unroll
            for (int ma = 0; ma < 2; ma++) {
                const int r = warp_m + ma * 16 + gid;
                ah[ma][0] = *(const uint32_t*)&Ash[r * KP + kofs];
                ah[ma][1] = *(const uint32_t*)&Ash[(r + 8) * KP + kofs];
                ah[ma][2] = *(const uint32_t*)&Ash[r * KP + kofs + 8];
                ah[ma][3] = *(const uint32_t*)&Ash[(r + 8) * KP + kofs + 8];
            }
            #pragma unroll
            for (int na = 0; na < 8; na++) {
                const int bn = warp_n + na * 8 + gid;
                uint32_t b0 = *(const uint32_t*)&Bsh[bn * KP + kofs];
                uint32_t b1 = *(const uint32_t*)&Bsh[bn * KP + kofs + 8];
                #pragma unroll
                for (int ma = 0; ma < 2; ma++) {
                    MMA_F16(acc[ma * 8 + na],
                            ah[ma][0], ah[ma][1], ah[ma][2], ah[ma][3], b0, b1);
                }
            }
        }

        if (have_next) {
            store_A(v, s ^ 1);
            asm volatile("cp.async.wait_group 0;" ::: "memory");
        }
        __syncthreads();
    }

    #pragma unroll
    for (int ma = 0; ma < 2; ma++) {
        const int mr0 = m0 + warp_m + ma * 16 + gid;
        const int mr1 = mr0 + 8;
        const int g0 = (mr0 < NN) ? __ldg(gidx + mr0) : 0;
        const int g1 = (mr1 < NN) ? __ldg(gidx + mr1) : 0;
        #pragma unroll
        for (int na = 0; na < 8; na++) {
            const int n = warp_n + na * 8 + t2;
            const float* a = acc[ma * 8 + na];
            if (mr0 < NN) {
                float2 b = *(const float2*)(g_gp + (size_t)g0 * FD + n);
                *(float2*)(out + (size_t)mr0 * FD + n) =
                    make_float2(a[0] + b.x, a[1] + b.y);
            }
            if (mr1 < NN) {
                float2 b = *(const float2*)(g_gp + (size_t)g1 * FD + n);
                *(float2*)(out + (size_t)mr1 * FD + n) =
                    make_float2(a[2] + b.x, a[3] + b.y);
            }
        }
    }
}

// ---------------------------------------------------------------------------
extern "C" void kernel_launch(void* const* d_in, const int* in_sizes, int n_in,
                              void* d_out, int out_size) {
    const float* node = (const float*)d_in[0];
    const float* edge = (const float*)d_in[1];
    const float* glob = (const float*)d_in[2];
    const float* Wn   = (const float*)d_in[3];
    const float* Wi   = (const float*)d_in[4];
    const float* Wo   = (const float*)d_in[5];
    const float* Wg   = (const float*)d_in[6];
    const float* bias = (const float*)d_in[7];
    const int* recv   = (const int*)d_in[8];
    const int* send   = (const int*)d_in[9];
    const int* gidx   = (const int*)d_in[10];
    float* out        = (float*)d_out;

    cudaFuncSetAttribute(gemm_mma_kernel,
                         cudaFuncAttributeMaxDynamicSharedMemorySize, GEMM_SMEM);

    // CSR build
    init_counts_kernel<<<(NN + 255) / 256, 256>>>();
    hist_kernel<<<(NE + 255) / 256, 256>>>(recv, send);
    scan_kernel<<<2, 1024>>>();
    fill_kernel<<<(NE + 255) / 256, 256>>>(recv, send);
    // aggregate via gather (MLP=16, scalar index loads)
    dim3 ggrid((NN + 7) / 8, 2);
    gather_kernel<<<ggrid, 256>>>(edge);
    // small preps
    b_split_kernel<<<(FD * 3 * FD + 255) / 256, 256>>>(Wn, Wi, Wo);
    globproj_kernel<<<(NG * FD + 7) / 8, 256>>>(glob, Wg, bias);
    // fused projection GEMM — fp16 single-term, pipelined
    gemm_mma_kernel<<<(NN + 127) / 128, 256, GEMM_SMEM>>>(node, gidx, out);
}

// round 17
// speedup vs baseline: 1.0148x; 1.0148x over previous
#include <cuda_runtime.h>
#include <cuda_fp16.h>
#include <cstdint>

#define NN 100000
#define NE 1600000
#define NG 50
#define FD 128

// Scratch (allocation-free rule: __device__ globals)
__device__ float g_gp[NG * FD];
__device__ __half g_nodeh[(size_t)NN * FD];     // node features, fp16
__device__ __half g_aggh_in[(size_t)NN * FD];   // agg_in, fp16
__device__ __half g_aggh_out[(size_t)NN * FD];  // agg_out, fp16
__device__ __half g_Bh[FD * 3 * FD];            // fp16 weights [n=128][k=384]
// CSR binning scratch
__device__ int g_cnt_in[NN],  g_cnt_out[NN];
__device__ int g_off_in[NN],  g_off_out[NN];
__device__ int g_cur_in[NN],  g_cur_out[NN];
__device__ int g_bin_in[NE],  g_bin_out[NE];

// ---------------------------------------------------------------------------
__device__ __forceinline__ uint32_t smem_u32(const void* p) {
    uint32_t a;
    asm("{ .reg .u64 t; cvta.to.shared.u64 t, %1; cvt.u32.u64 %0, t; }"
        : "=r"(a) : "l"(p));
    return a;
}
__device__ __forceinline__ uint32_t pack_f16(float x, float y) {
    __half2 t = __floats2half2_rn(x, y);   // .x = low half
    return *(uint32_t*)&t;
}

// ---------------------------------------------------------------------------
// CSR build (verbatim R16)
// ---------------------------------------------------------------------------
__global__ void init_counts_kernel() {
    int i = blockIdx.x * blockDim.x + threadIdx.x;
    if (i < NN) { g_cnt_in[i] = 0; g_cnt_out[i] = 0; }
}

__global__ void hist_kernel(const int* __restrict__ recv,
                            const int* __restrict__ send) {
    int e = blockIdx.x * blockDim.x + threadIdx.x;
    if (e < NE) {
        atomicAdd(&g_cnt_in[recv[e]], 1);
        atomicAdd(&g_cnt_out[send[e]], 1);
    }
}

#define SCAN_C 98
__global__ void scan_kernel() {
    const int* cnt = blockIdx.x ? g_cnt_out : g_cnt_in;
    int* off = blockIdx.x ? g_off_out : g_off_in;
    int* cur = blockIdx.x ? g_cur_out : g_cur_in;
    const int tid = threadIdx.x;
    const int base = tid * SCAN_C;
    int s = 0;
    for (int i = 0; i < SCAN_C; i++) {
        int idx = base + i;
        if (idx < NN) s += cnt[idx];
    }
    __shared__ int sh[1024];
    sh[tid] = s;
    __syncthreads();
    for (int o = 1; o < 1024; o <<= 1) {
        int v = (tid >= o) ? sh[tid - o] : 0;
        __syncthreads();
        sh[tid] += v;
        __syncthreads();
    }
    int run = sh[tid] - s;
    for (int i = 0; i < SCAN_C; i++) {
        int idx = base + i;
        if (idx < NN) {
            off[idx] = run;
            cur[idx] = run;
            run += cnt[idx];
        }
    }
}

__global__ void fill_kernel(const int* __restrict__ recv,
                            const int* __restrict__ send) {
    int e = blockIdx.x * blockDim.x + threadIdx.x;
    if (e < NE) {
        int p = atomicAdd(&g_cur_in[recv[e]], 1);
        g_bin_in[p] = e;
        int q = atomicAdd(&g_cur_out[send[e]], 1);
        g_bin_out[q] = e;
    }
}

// ---------------------------------------------------------------------------
// Gather: warp per node per direction; fp32 accumulate, write fp16 directly
// (same __floats2half2_rn rounding the GEMM's store_A used to apply).
// ---------------------------------------------------------------------------
__global__ void __launch_bounds__(256)
gather_kernel(const float* __restrict__ ef) {
    const int warp = threadIdx.x >> 5;
    const int lane = threadIdx.x & 31;
    const int node = blockIdx.x * 8 + warp;
    if (node >= NN) return;
    const int* off; const int* cnt; const int* bin; __half* aggh;
    if (blockIdx.y == 0) { off = g_off_in;  cnt = g_cnt_in;  bin = g_bin_in;  aggh = g_aggh_in; }
    else                 { off = g_off_out; cnt = g_cnt_out; bin = g_bin_out; aggh = g_aggh_out; }

    const int start = __ldg(off + node);
    const int end   = start + __ldg(cnt + node);
    const float4* ef4 = (const float4*)ef;
    float4 acc = make_float4(0.f, 0.f, 0.f, 0.f);

    int j = start;
    for (; j + 4 <= end; j += 4) {
        int i0 = __ldg(bin + j), i1 = __ldg(bin + j + 1);
        int i2 = __ldg(bin + j + 2), i3 = __ldg(bin + j + 3);
        float4 v0 = __ldg(ef4 + (size_t)i0 * 32 + lane);
        float4 v1 = __ldg(ef4 + (size_t)i1 * 32 + lane);
        float4 v2 = __ldg(ef4 + (size_t)i2 * 32 + lane);
        float4 v3 = __ldg(ef4 + (size_t)i3 * 32 + lane);
        acc.x += (v0.x + v1.x) + (v2.x + v3.x);
        acc.y += (v0.y + v1.y) + (v2.y + v3.y);
        acc.z += (v0.z + v1.z) + (v2.z + v3.z);
        acc.w += (v0.w + v1.w) + (v2.w + v3.w);
    }
    for (; j < end; j++) {
        int i0 = __ldg(bin + j);
        float4 v = __ldg(ef4 + (size_t)i0 * 32 + lane);
        acc.x += v.x; acc.y += v.y; acc.z += v.z; acc.w += v.w;
    }
    uint2 hv = make_uint2(pack_f16(acc.x, acc.y), pack_f16(acc.z, acc.w));
    *(uint2*)(aggh + (size_t)node * FD + lane * 4) = hv;
}

// ---------------------------------------------------------------------------
// node features fp32 -> fp16 (one pass)
// ---------------------------------------------------------------------------
__global__ void node_conv_kernel(const float* __restrict__ node) {
    size_t t = (size_t)blockIdx.x * blockDim.x + threadIdx.x;
    if (t * 4 >= (size_t)NN * FD) return;
    float4 v = *(const float4*)(node + t * 4);
    *(uint2*)(g_nodeh + t * 4) = make_uint2(pack_f16(v.x, v.y), pack_f16(v.z, v.w));
}

// ---------------------------------------------------------------------------
// globproj (verbatim R16)
// ---------------------------------------------------------------------------
__global__ void __launch_bounds__(256)
globproj_kernel(const float* __restrict__ gf,
                const float* __restrict__ Wg,
                const float* __restrict__ bias) {
    const int warp = threadIdx.x >> 5;
    const int lane = threadIdx.x & 31;
    const int idx = blockIdx.x * 8 + warp;
    if (idx >= NG * FD) return;
    const int g = idx >> 7, n = idx & 127;
    const float* gr = gf + (size_t)g * FD;
    const float* wr = Wg + (size_t)n * FD;
    float s = 0.f;
    #pragma unroll
    for (int q = 0; q < 4; q++)
        s += __ldg(gr + lane + q * 32) * __ldg(wr + lane + q * 32);
    #pragma unroll
    for (int o = 16; o > 0; o >>= 1) s += __shfl_xor_sync(0xFFFFFFFFu, s, o);
    if (lane == 0) g_gp[idx] = s + __ldg(bias + n);
}

// ---------------------------------------------------------------------------
// B -> fp16, layout [n][384] (verbatim R16)
// ---------------------------------------------------------------------------
__global__ void b_split_kernel(const float* __restrict__ Wn,
                               const float* __restrict__ Wi,
                               const float* __restrict__ Wo) {
    int idx = blockIdx.x * blockDim.x + threadIdx.x;
    if (idx >= FD * 3 * FD) return;
    int n = idx / (3 * FD);
    int k = idx % (3 * FD);
    int seg = k >> 7, kk = k & 127;
    const float* W = (seg == 0) ? Wn : (seg == 1) ? Wi : Wo;
    g_Bh[idx] = __float2half_rn(W[n * FD + kk]);
}

// ---------------------------------------------------------------------------
// GEMM: mma.sync m16n8k16 fp16 single-term; A and B BOTH via cp.async
// (A pre-converted to fp16), symmetric 2-stage pipeline, one commit/chunk.
// ---------------------------------------------------------------------------
#define KP 40
#define TILE_BYTES (128 * KP * 2)        // 10240
#define STAGE_BYTES (2 * TILE_BYTES)     // 20480 (A + B)
#define AH_OFF(s) ((s) * STAGE_BYTES)
#define BH_OFF(s) ((s) * STAGE_BYTES + TILE_BYTES)
#define GEMM_SMEM (2 * STAGE_BYTES)      // 40960

#define MMA_F16(acc, a0, a1, a2, a3, b0, b1)                                \
    asm volatile(                                                           \
        "mma.sync.aligned.m16n8k16.row.col.f32.f16.f16.f32 "                \
        "{%0,%1,%2,%3}, {%4,%5,%6,%7}, {%8,%9}, {%0,%1,%2,%3};"             \
        : "+f"(acc[0]), "+f"(acc[1]), "+f"(acc[2]), "+f"(acc[3])            \
        : "r"(a0), "r"(a1), "r"(a2), "r"(a3), "r"(b0), "r"(b1))

__global__ void __launch_bounds__(256, 2)
gemm_mma_kernel(const int* __restrict__ gidx, float* __restrict__ out) {
    extern __shared__ __align__(16) char smem[];
    const uint32_t sb = smem_u32(smem);
    __half* const smh = (__half*)smem;

    const int tid    = threadIdx.x;
    const int wid    = tid >> 5;
    const int lane   = tid & 31;
    const int gid    = lane >> 2;
    const int t2     = (lane & 3) * 2;
    const int warp_m = (wid & 3) * 32;
    const int warp_n = (wid >> 2) * 64;
    const int m0     = blockIdx.x * 128;

    float acc[16][4];
    #pragma unroll
    for (int i = 0; i < 16; i++)
        #pragma unroll
        for (int j = 0; j < 4; j++) acc[i][j] = 0.f;

    // chunk loader: A and B tiles, 4 cp.asyncs per thread, ONE commit
    auto load_chunk = [&](int kb, int st) {
        const int seg   = kb >> 2;
        const int kloc  = (kb & 3) * 32;
        const int kglob = seg * FD + kloc;
        const __half* Xh = (seg == 0) ? g_nodeh
                         : (seg == 1) ? g_aggh_in : g_aggh_out;
        #pragma unroll
        for (int i = 0; i < 2; i++) {
            int c = tid * 2 + i;            // 0..511 granules of 16B
            int row = c >> 2, sub = c & 3;
            uint32_t doff = (uint32_t)(row * (KP * 2) + sub * 16);
            // A: clamp pad rows to a valid address (results discarded in epilogue)
            int gm = m0 + row; if (gm >= NN) gm = NN - 1;
            const __half* sa = Xh + (size_t)gm * FD + kloc + sub * 8;
            const __half* sbp = g_Bh + (size_t)row * (3 * FD) + kglob + sub * 8;
            asm volatile("cp.async.cg.shared.global [%0], [%1], 16;"
                         :: "r"(sb + AH_OFF(st) + doff), "l"(sa) : "memory");
            asm volatile("cp.async.cg.shared.global [%0], [%1], 16;"
                         :: "r"(sb + BH_OFF(st) + doff), "l"(sbp) : "memory");
        }
        asm volatile("cp.async.commit_group;" ::: "memory");
    };

    load_chunk(0, 0);
    asm volatile("cp.async.wait_group 0;" ::: "memory");
    __syncthreads();

    #pragma unroll 1
    for (int kb = 0; kb < 12; kb++) {
        const int s = kb & 1;
        const bool have_next = (kb < 11);
        if (have_next) load_chunk(kb + 1, s ^ 1);

        const __half* Ash = smh + (AH_OFF(s) >> 1);
        const __half* Bsh = smh + (BH_OFF(s) >> 1);
        #pragma unroll
        for (int ks = 0; ks < 2; ks++) {
            const int kofs = ks * 16 + t2;
            uint32_t ah[2][4];
            #pragma unroll
            for (int ma = 0; ma < 2; ma++) {
                const int r = warp_m + ma * 16 + gid;
                ah[ma][0] = *(const uint32_t*)&Ash[r * KP + kofs];
                ah[ma][1] = *(const uint32_t*)&Ash[(r + 8) * KP + kofs];
                ah[ma][2] = *(const uint32_t*)&Ash[r * KP + kofs + 8];
                ah[ma][3] = *(const uint32_t*)&Ash[(r + 8) * KP + kofs + 8];
            }
            #pragma unroll
            for (int na = 0; na < 8; na++) {
                const int bn = warp_n + na * 8 + gid;
                uint32_t b0 = *(const uint32_t*)&Bsh[bn * KP + kofs];
                uint32_t b1 = *(const uint32_t*)&Bsh[bn * KP + kofs + 8];
                #pragma unroll
                for (int ma = 0; ma < 2; ma++) {
                    MMA_F16(acc[ma * 8 + na],
                            ah[ma][0], ah[ma][1], ah[ma][2], ah[ma][3], b0, b1);
                }
            }
        }

        if (have_next)
            asm volatile("cp.async.wait_group 0;" ::: "memory");
        __syncthreads();
    }

    // ---- epilogue: + gp[graph_idx[m]] (bias folded), store ----
    #pragma unroll
    for (int ma = 0; ma < 2; ma++) {
        const int mr0 = m0 + warp_m + ma * 16 + gid;
        const int mr1 = mr0 + 8;
        const int g0 = (mr0 < NN) ? __ldg(gidx + mr0) : 0;
        const int g1 = (mr1 < NN) ? __ldg(gidx + mr1) : 0;
        #pragma unroll
        for (int na = 0; na < 8; na++) {
            const int n = warp_n + na * 8 + t2;
            const float* a = acc[ma * 8 + na];
            if (mr0 < NN) {
                float2 b = *(const float2*)(g_gp + (size_t)g0 * FD + n);
                *(float2*)(out + (size_t)mr0 * FD + n) =
                    make_float2(a[0] + b.x, a[1] + b.y);
            }
            if (mr1 < NN) {
                float2 b = *(const float2*)(g_gp + (size_t)g1 * FD + n);
                *(float2*)(out + (size_t)mr1 * FD + n) =
                    make_float2(a[2] + b.x, a[3] + b.y);
            }
        }
    }
}

// ---------------------------------------------------------------------------
extern "C" void kernel_launch(void* const* d_in, const int* in_sizes, int n_in,
                              void* d_out, int out_size) {
    const float* node = (const float*)d_in[0];
    const float* edge = (const float*)d_in[1];
    const float* glob = (const float*)d_in[2];
    const float* Wn   = (const float*)d_in[3];
    const float* Wi   = (const float*)d_in[4];
    const float* Wo   = (const float*)d_in[5];
    const float* Wg   = (const float*)d_in[6];
    const float* bias = (const float*)d_in[7];
    const int* recv   = (const int*)d_in[8];
    const int* send   = (const int*)d_in[9];
    const int* gidx   = (const int*)d_in[10];
    float* out        = (float*)d_out;

    cudaFuncSetAttribute(gemm_mma_kernel,
                         cudaFuncAttributeMaxDynamicSharedMemorySize, GEMM_SMEM);

    // CSR build
    init_counts_kernel<<<(NN + 255) / 256, 256>>>();
    hist_kernel<<<(NE + 255) / 256, 256>>>(recv, send);
    scan_kernel<<<2, 1024>>>();
    fill_kernel<<<(NE + 255) / 256, 256>>>(recv, send);
    // aggregate via gather -> fp16 agg
    dim3 ggrid((NN + 7) / 8, 2);
    gather_kernel<<<ggrid, 256>>>(edge);
    // conversions / small preps
    node_conv_kernel<<<(int)(((size_t)NN * FD / 4 + 255) / 256), 256>>>(node);
    b_split_kernel<<<(FD * 3 * FD + 255) / 256, 256>>>(Wn, Wi, Wo);
    globproj_kernel<<<(NG * FD + 7) / 8, 256>>>(glob, Wg, bias);
    // fused projection GEMM — pure cp.async pipeline, fp16 single-term
    gemm_mma_kernel<<<(NN + 127) / 128, 256, GEMM_SMEM>>>(gidx, out);
}